// round 3
// baseline (speedup 1.0000x reference)
#include <cuda_runtime.h>
#include <math.h>

// YOLO loss: preds/targets [N,7,7,30] fp32 -> scalar fp32.
// D = 2*5 + 20 = 30 floats per cell. Streaming reduction, HBM-bound.

constexpr int D      = 30;   // floats per cell
constexpr int DP     = 31;   // padded smem row (gcd(31,32)=1 -> conflict-free)
constexpr int BLK    = 128;  // threads per block == cells per block
constexpr float LAMBDA_NOOBJ = 0.5f;
constexpr float EPS_IOU      = 1e-10f;

__device__ double g_sum;

__global__ void yolo_zero_kernel() { g_sum = 0.0; }

__global__ void __launch_bounds__(BLK)
yolo_main_kernel(const float* __restrict__ preds,
                 const float* __restrict__ targets,
                 int n_cells)
{
    __shared__ float sp[BLK * DP];
    __shared__ float st[BLK * DP];
    __shared__ float warp_sums[BLK / 32];

    const int tid   = threadIdx.x;
    const int cell0 = blockIdx.x * BLK;

    // ---- Stage 1: coalesced global -> smem (scatter into padded layout) ----
    if (cell0 + BLK <= n_cells) {
        // Full block: vectorized float4 path. BLK*D = 3840 floats = 960 float4.
        const float4* p4 = reinterpret_cast<const float4*>(preds   + (size_t)cell0 * D);
        const float4* t4 = reinterpret_cast<const float4*>(targets + (size_t)cell0 * D);
        #pragma unroll
        for (int it = 0; it < (BLK * D / 4 + BLK - 1) / BLK; ++it) {
            int i = tid + it * BLK;
            if (i < BLK * D / 4) {
                float4 vp = p4[i];
                float4 vt = t4[i];
                int f = i * 4;
                int c = f / D;
                int j = f - c * D;
                sp[c * DP + j] = vp.x;  st[c * DP + j] = vt.x;
                if (++j == D) { j = 0; ++c; }
                sp[c * DP + j] = vp.y;  st[c * DP + j] = vt.y;
                if (++j == D) { j = 0; ++c; }
                sp[c * DP + j] = vp.z;  st[c * DP + j] = vt.z;
                if (++j == D) { j = 0; ++c; }
                sp[c * DP + j] = vp.w;  st[c * DP + j] = vt.w;
            }
        }
    } else {
        // Tail block: guarded scalar path.
        int lim = (n_cells - cell0) * D;
        for (int f = tid; f < BLK * D; f += BLK) {
            int c = f / D;
            int j = f - c * D;
            float vp = 0.f, vt = 0.f;
            if (f < lim) {
                vp = preds  [(size_t)cell0 * D + f];
                vt = targets[(size_t)cell0 * D + f];
            }
            sp[c * DP + j] = vp;
            st[c * DP + j] = vt;
        }
    }
    __syncthreads();

    // ---- Stage 2: per-cell loss (one thread per cell, conflict-free smem) ----
    float loss = 0.0f;
    if (cell0 + tid < n_cells) {
        const float* p = sp + tid * DP;
        const float* t = st + tid * DP;

        // IoU for the 2 paired boxes
        float iou[2];
        #pragma unroll
        for (int b = 0; b < 2; ++b) {
            float px = p[5*b + 0], py = p[5*b + 1], pw = p[5*b + 2], ph = p[5*b + 3];
            float tx = t[5*b + 0], ty = t[5*b + 1], tw = t[5*b + 2], th = t[5*b + 3];
            float iw = fminf(px + 0.5f*pw, tx + 0.5f*tw) - fmaxf(px - 0.5f*pw, tx - 0.5f*tw);
            float ih = fminf(py + 0.5f*ph, ty + 0.5f*th) - fmaxf(py - 0.5f*ph, ty - 0.5f*th);
            iw = fmaxf(0.0f, iw);
            ih = fmaxf(0.0f, ih);
            float inter = iw * ih;
            float uni   = pw * ph + tw * th - inter;
            iou[b] = inter / (uni + EPS_IOU);
        }

        // argmax over 2 boxes (first max on ties -> strict >)
        int sel = (iou[1] > iou[0]) ? 1 : 0;

        // coord loss (masked by has_obj = targets[...,4] > 0)
        bool has_obj = (t[4] > 0.0f);
        float dx = p[5*sel + 0] - t[5*sel + 0];
        float dy = p[5*sel + 1] - t[5*sel + 1];
        if (has_obj) loss += dx*dx + dy*dy;

        // class loss + argmax of target class (first max on ties)
        float best = t[10];
        int   gt   = 10;
        #pragma unroll
        for (int c = 0; c < 20; ++c) {
            float pc = p[10 + c];
            float tc = t[10 + c];
            float d  = pc - tc;
            loss += d * d;
            if (tc > best) { best = tc; gt = 10 + c; }
        }
        float pcgt = p[gt];

        // confidence loss: w * (iou*pcgt - iou)^2 = w * iou^2 * (pcgt-1)^2
        float g = pcgt - 1.0f;
        #pragma unroll
        for (int b = 0; b < 2; ++b) {
            float w    = (b == sel) ? 1.0f : LAMBDA_NOOBJ;
            float diff = iou[b] * g;
            loss += w * diff * diff;
        }
    }

    // ---- Stage 3: reduction ----
    #pragma unroll
    for (int off = 16; off > 0; off >>= 1)
        loss += __shfl_xor_sync(0xFFFFFFFFu, loss, off);
    if ((tid & 31) == 0) warp_sums[tid >> 5] = loss;
    __syncthreads();
    if (tid == 0) {
        double s = 0.0;
        #pragma unroll
        for (int w = 0; w < BLK / 32; ++w) s += (double)warp_sums[w];
        atomicAdd(&g_sum, s);
    }
}

__global__ void yolo_finalize_kernel(float* __restrict__ out, int N)
{
    out[0] = (float)(g_sum / (double)N);
}

extern "C" void kernel_launch(void* const* d_in, const int* in_sizes, int n_in,
                              void* d_out, int out_size)
{
    const float* preds   = (const float*)d_in[0];
    const float* targets = (const float*)d_in[1];
    float* out = (float*)d_out;

    int total   = in_sizes[0];          // N*7*7*30
    int n_cells = total / D;            // N*49
    int N       = total / (7 * 7 * D);  // batch

    int grid = (n_cells + BLK - 1) / BLK;

    yolo_zero_kernel<<<1, 1>>>();
    yolo_main_kernel<<<grid, BLK>>>(preds, targets, n_cells);
    yolo_finalize_kernel<<<1, 1>>>(out, N);
}